// round 8
// baseline (speedup 1.0000x reference)
#include <cuda_runtime.h>

// Dilation1D: out[r] = max_{j=0..10} x[r-5+j] + h[j],  h[j] = -(j-5)^2/(4*scale)
// Symmetric-tap form: out[r] = max(x[r], max_{d=1..5} max(x[r-d],x[r+d]) + h_d)
//
// Smem-staged tile: block stages 1024+16 floats with ONE perfectly coalesced
// float4 LDG per thread (zero redundant gmem traffic, structural-minimum L1tex
// wavefronts), then each thread reads its 20-float window via 5 contiguous,
// conflict-free LDS.128 and writes 4 outputs with one coalesced STG.128.

#define BLOCK 256
#define VEC   4
#define TILE  (BLOCK * VEC)          // 1024 floats per block
#define HALO  8
#define SMF   (TILE + 2 * HALO)      // 1040 floats staged

__global__ __launch_bounds__(BLOCK) void dilate1d_kernel(
    const float* __restrict__ x,
    const float* __restrict__ scale_p,
    float* __restrict__ out,
    int n)
{
    __shared__ float sm[SMF];

    const int t    = threadIdx.x;
    const int base = blockIdx.x * TILE;
    const float NEG_INF = __int_as_float(0xff800000);

    const bool interior = (base >= HALO) && (base + TILE + HALO <= n);

    if (interior) {
        // Stage [base-8, base+1032): 260 float4s, 16B-aligned source.
        const float4* src = reinterpret_cast<const float4*>(x + base - HALO);
        float4*       dst = reinterpret_cast<float4*>(sm);
        dst[t] = src[t];
        if (t < (SMF / 4 - BLOCK))            // 4 threads stage the last 4 chunks
            dst[BLOCK + t] = src[BLOCK + t];
    } else {
        // First/last block: scalar guarded staging with -inf padding.
        for (int k = t; k < SMF; k += BLOCK) {
            int idx = base - HALO + k;
            sm[k] = (idx >= 0 && idx < n) ? x[idx] : NEG_INF;
        }
    }
    __syncthreads();

    const float s = __ldg(scale_p);
    const float c = -0.25f / s;
    const float h1 =  1.0f * c;
    const float h2 =  4.0f * c;
    const float h3 =  9.0f * c;
    const float h4 = 16.0f * c;
    const float h5 = 25.0f * c;

    // Window w[k] = sm[t*4 + k] = x[i - 8 + k], i = base + t*4.
    // Output v (0..3) uses w[v+3 .. v+13]; max idx 16 < 20.
    float w[20];
    const float4* smv = reinterpret_cast<const float4*>(sm + t * VEC); // 16B aligned
    #pragma unroll
    for (int q = 0; q < 5; q++) {
        float4 v = smv[q];                    // contiguous across lanes: conflict-free
        w[q * 4 + 0] = v.x;
        w[q * 4 + 1] = v.y;
        w[q * 4 + 2] = v.z;
        w[q * 4 + 3] = v.w;
    }

    float o[VEC];
    #pragma unroll
    for (int v = 0; v < VEC; v++) {
        float r = w[v + 8];                               // center tap, h=0
        r = fmaxf(r, fmaxf(w[v + 7], w[v + 9])  + h1);
        r = fmaxf(r, fmaxf(w[v + 6], w[v + 10]) + h2);
        r = fmaxf(r, fmaxf(w[v + 5], w[v + 11]) + h3);
        r = fmaxf(r, fmaxf(w[v + 4], w[v + 12]) + h4);
        r = fmaxf(r, fmaxf(w[v + 3], w[v + 13]) + h5);
        o[v] = r;
    }

    const int i = base + t * VEC;
    if (i + VEC <= n) {
        // Streaming store: output never re-read; don't thrash L2.
        __stcs(reinterpret_cast<float4*>(out + i), make_float4(o[0], o[1], o[2], o[3]));
    } else {
        #pragma unroll
        for (int v = 0; v < VEC; v++)
            if (i + v < n) out[i + v] = o[v];
    }
}

extern "C" void kernel_launch(void* const* d_in, const int* in_sizes, int n_in,
                              void* d_out, int out_size)
{
    const float* x       = (const float*)d_in[0];
    const float* scale_p = (const float*)d_in[1];
    float*       out     = (float*)d_out;
    int n = in_sizes[0];

    int blocks = (n + TILE - 1) / TILE;
    dilate1d_kernel<<<blocks, BLOCK>>>(x, scale_p, out, n);
}

// round 9
// speedup vs baseline: 1.0773x; 1.0773x over previous
#include <cuda_runtime.h>

// Dilation1D: out[r] = max_{j=0..10} x[r-5+j] + h[j],  h[j] = -(j-5)^2/(4*scale)
// Symmetric-tap form: out[r] = max(x[r], max_{d=1..5} max(x[r-d],x[r+d]) + h_d)
//
// R9: identical memory structure to R6 (VEC=4 blocked, perfectly coalesced
// float4 loads/stores), but BLOCK=1024 with launch_bounds(1024,2):
// 2 CTAs/SM instead of 8 at the same warp count. Per the B300 cross-CTA
// L1tex-queue spread model (spr = 1.10 + 25*(oe*MLP_p1-16)/T_CTA), dropping
// oe from 8 to 2 moves oe*MLP_p1 from ~40 to ~10 (<16) -> floor spread.

#define VEC   4
#define BLOCK 1024
#define TILE  (BLOCK * VEC)

__global__ __launch_bounds__(BLOCK, 2) void dilate1d_kernel(
    const float* __restrict__ x,
    const float* __restrict__ scale_p,
    float* __restrict__ out,
    int n)
{
    int i = (blockIdx.x * BLOCK + threadIdx.x) * VEC;
    if (i >= n) return;

    const float s = __ldg(scale_p);
    const float c = -0.25f / s;
    const float h1 =  1.0f * c;
    const float h2 =  4.0f * c;
    const float h3 =  9.0f * c;
    const float h4 = 16.0f * c;
    const float h5 = 25.0f * c;

    const float NEG_INF = __int_as_float(0xff800000);

    // Window w[k] = x[i - 8 + k], k = 0..19.
    // Output v (0..3) needs x[i+v-5 .. i+v+5] = w[v+3 .. v+13]; max idx 16 < 20.
    float w[20];

    if (i >= 8 && i + 12 <= n) {
        // 5 coalesced float4 loads (lane stride 16B == load width).
        const float4* p = reinterpret_cast<const float4*>(x + i - 8);
        #pragma unroll
        for (int q = 0; q < 5; q++) {
            float4 v = p[q];
            w[q * 4 + 0] = v.x;
            w[q * 4 + 1] = v.y;
            w[q * 4 + 2] = v.z;
            w[q * 4 + 3] = v.w;
        }
    } else {
        // Boundary path: scalar guarded loads with -inf padding (matches reference).
        #pragma unroll
        for (int k = 0; k < 20; k++) {
            int idx = i - 8 + k;
            w[k] = (idx >= 0 && idx < n) ? x[idx] : NEG_INF;
        }
    }

    float o[VEC];
    #pragma unroll
    for (int v = 0; v < VEC; v++) {
        float r = w[v + 8];                               // center tap, h=0
        r = fmaxf(r, fmaxf(w[v + 7], w[v + 9])  + h1);
        r = fmaxf(r, fmaxf(w[v + 6], w[v + 10]) + h2);
        r = fmaxf(r, fmaxf(w[v + 5], w[v + 11]) + h3);
        r = fmaxf(r, fmaxf(w[v + 4], w[v + 12]) + h4);
        r = fmaxf(r, fmaxf(w[v + 3], w[v + 13]) + h5);
        o[v] = r;
    }

    if (i + VEC <= n) {
        // Streaming store: output never re-read.
        __stcs(reinterpret_cast<float4*>(out + i), make_float4(o[0], o[1], o[2], o[3]));
    } else {
        #pragma unroll
        for (int v = 0; v < VEC; v++)
            if (i + v < n) out[i + v] = o[v];
    }
}

extern "C" void kernel_launch(void* const* d_in, const int* in_sizes, int n_in,
                              void* d_out, int out_size)
{
    const float* x       = (const float*)d_in[0];
    const float* scale_p = (const float*)d_in[1];
    float*       out     = (float*)d_out;
    int n = in_sizes[0];

    int blocks = (n + TILE - 1) / TILE;
    dilate1d_kernel<<<blocks, BLOCK>>>(x, scale_p, out, n);
}

// round 10
// speedup vs baseline: 1.1729x; 1.0888x over previous
#include <cuda_runtime.h>

// Dilation1D: out[r] = max_{j=0..10} x[r-5+j] + h[j],  h[j] = -(j-5)^2/(4*scale)
// Symmetric-tap form: out[r] = max(x[r], max_{d=1..5} max(x[r-d],x[r+d]) + h_d)
//
// R10: R6's perfectly-coalesced VEC=4 pattern, but 2-way ILP: each thread
// computes two float4 output groups 1024 floats apart (block tile = 2048).
// All 10 LDG.128 are front-batched -> MLP/thread 5 -> 10, threads halved,
// wavefronts/output unchanged (structural minimum for this halo scheme).

#define BLOCK 256
#define SEG   (BLOCK * 4)        // 1024 floats per segment
#define TILE  (2 * SEG)          // 2048 floats per block

__global__ __launch_bounds__(BLOCK, 4) void dilate1d_kernel(
    const float* __restrict__ x,
    const float* __restrict__ scale_p,
    float* __restrict__ out,
    int n)
{
    const int t    = threadIdx.x;
    const int base = blockIdx.x * TILE;
    const int gA   = base + t * 4;          // first output group
    const int gB   = gA + SEG;              // second output group

    const float s = __ldg(scale_p);
    const float c = -0.25f / s;
    const float h1 =  1.0f * c;
    const float h2 =  4.0f * c;
    const float h3 =  9.0f * c;
    const float h4 = 16.0f * c;
    const float h5 = 25.0f * c;
    const float NEG_INF = __int_as_float(0xff800000);

    float wA[20], wB[20];

    const bool interior = (base >= 8) && (base + TILE + 8 <= n);

    if (interior) {
        // 10 front-batched, perfectly coalesced float4 loads (lane stride 16B).
        const float4* pA = reinterpret_cast<const float4*>(x + gA - 8);
        const float4* pB = reinterpret_cast<const float4*>(x + gB - 8);
        float4 vA[5], vB[5];
        #pragma unroll
        for (int q = 0; q < 5; q++) vA[q] = pA[q];
        #pragma unroll
        for (int q = 0; q < 5; q++) vB[q] = pB[q];
        #pragma unroll
        for (int q = 0; q < 5; q++) {
            wA[q*4+0] = vA[q].x; wA[q*4+1] = vA[q].y;
            wA[q*4+2] = vA[q].z; wA[q*4+3] = vA[q].w;
            wB[q*4+0] = vB[q].x; wB[q*4+1] = vB[q].y;
            wB[q*4+2] = vB[q].z; wB[q*4+3] = vB[q].w;
        }
    } else {
        // Boundary blocks (first/last): guarded scalar loads, -inf pad.
        #pragma unroll
        for (int k = 0; k < 20; k++) {
            int ia = gA - 8 + k;
            int ib = gB - 8 + k;
            wA[k] = (ia >= 0 && ia < n) ? x[ia] : NEG_INF;
            wB[k] = (ib >= 0 && ib < n) ? x[ib] : NEG_INF;
        }
    }

    float oA[4], oB[4];
    #pragma unroll
    for (int v = 0; v < 4; v++) {
        float r = wA[v + 8];                               // center tap, h=0
        r = fmaxf(r, fmaxf(wA[v + 7], wA[v + 9])  + h1);
        r = fmaxf(r, fmaxf(wA[v + 6], wA[v + 10]) + h2);
        r = fmaxf(r, fmaxf(wA[v + 5], wA[v + 11]) + h3);
        r = fmaxf(r, fmaxf(wA[v + 4], wA[v + 12]) + h4);
        r = fmaxf(r, fmaxf(wA[v + 3], wA[v + 13]) + h5);
        oA[v] = r;

        float q2 = wB[v + 8];
        q2 = fmaxf(q2, fmaxf(wB[v + 7], wB[v + 9])  + h1);
        q2 = fmaxf(q2, fmaxf(wB[v + 6], wB[v + 10]) + h2);
        q2 = fmaxf(q2, fmaxf(wB[v + 5], wB[v + 11]) + h3);
        q2 = fmaxf(q2, fmaxf(wB[v + 4], wB[v + 12]) + h4);
        q2 = fmaxf(q2, fmaxf(wB[v + 3], wB[v + 13]) + h5);
        oB[v] = q2;
    }

    if (gA + 4 <= n) {
        __stcs(reinterpret_cast<float4*>(out + gA), make_float4(oA[0], oA[1], oA[2], oA[3]));
    } else {
        #pragma unroll
        for (int v = 0; v < 4; v++) if (gA + v < n) out[gA + v] = oA[v];
    }
    if (gB + 4 <= n) {
        __stcs(reinterpret_cast<float4*>(out + gB), make_float4(oB[0], oB[1], oB[2], oB[3]));
    } else {
        #pragma unroll
        for (int v = 0; v < 4; v++) if (gB + v < n) out[gB + v] = oB[v];
    }
}

extern "C" void kernel_launch(void* const* d_in, const int* in_sizes, int n_in,
                              void* d_out, int out_size)
{
    const float* x       = (const float*)d_in[0];
    const float* scale_p = (const float*)d_in[1];
    float*       out     = (float*)d_out;
    int n = in_sizes[0];

    int blocks = (n + TILE - 1) / TILE;
    dilate1d_kernel<<<blocks, BLOCK>>>(x, scale_p, out, n);
}

// round 12
// speedup vs baseline: 1.2362x; 1.0539x over previous
#include <cuda_runtime.h>

// Dilation1D: out[r] = max_{j=0..10} x[r-5+j] + h[j],  h[j] = -(j-5)^2/(4*scale)
// Symmetric-tap form: out[r] = max(x[r], max_{d=1..5} max(x[r-d],x[r+d]) + h_d)
//
// R11 == R1 (measured optimum, re-confirm): VEC=8 blocked windows, 6 aligned
// float4 loads + 2 float4 plain stores per thread, BLOCK=256.
// Six structurally different designs (VEC4 coalesced, shuffle-halo, smem tile,
// 1024-thread CTAs, 2-way ILP) all plateau at ~41-52us with DRAM rate pinned
// at <=5.4 TB/s: the kernel is at the HBM mixed read+write stream ceiling
// (~67% of read-spec), with DRAM traffic already compulsory-minimal (~219 MB).
// R1's config achieved the highest sustained DRAM rate (5388 GB/s) and the
// best time (40.7us ncu / 44.2us bench).

#define VEC   8
#define BLOCK 256

__global__ __launch_bounds__(BLOCK) void dilate1d_kernel(
    const float* __restrict__ x,
    const float* __restrict__ scale_p,
    float* __restrict__ out,
    int n)
{
    int i = (blockIdx.x * BLOCK + threadIdx.x) * VEC;
    if (i >= n) return;

    const float s = *scale_p;
    const float c = -0.25f / s;
    const float h1 =  1.0f * c;
    const float h2 =  4.0f * c;
    const float h3 =  9.0f * c;
    const float h4 = 16.0f * c;
    const float h5 = 25.0f * c;

    const float NEG_INF = __int_as_float(0xff800000);

    // Window w[k] = x[i - 8 + k], k = 0..23 (covers x[i-5 .. i+12] needed,
    // rounded out to aligned float4 chunks).
    float w[24];

    if (i >= 8 && i + 16 <= n) {
        // Fast path: 6 aligned float4 loads (i is a multiple of 8 -> 32B aligned).
        const float4* p = reinterpret_cast<const float4*>(x + i - 8);
        #pragma unroll
        for (int q = 0; q < 6; q++) {
            float4 v = p[q];
            w[q * 4 + 0] = v.x;
            w[q * 4 + 1] = v.y;
            w[q * 4 + 2] = v.z;
            w[q * 4 + 3] = v.w;
        }
    } else {
        // Boundary path: scalar loads with -inf padding (matches reference).
        #pragma unroll
        for (int k = 0; k < 24; k++) {
            int idx = i - 8 + k;
            w[k] = (idx >= 0 && idx < n) ? x[idx] : NEG_INF;
        }
    }

    float o[VEC];
    #pragma unroll
    for (int v = 0; v < VEC; v++) {
        // center tap: h[5] = 0
        float r = w[v + 8];
        r = fmaxf(r, fmaxf(w[v + 7], w[v + 9])  + h1);
        r = fmaxf(r, fmaxf(w[v + 6], w[v + 10]) + h2);
        r = fmaxf(r, fmaxf(w[v + 5], w[v + 11]) + h3);
        r = fmaxf(r, fmaxf(w[v + 4], w[v + 12]) + h4);
        r = fmaxf(r, fmaxf(w[v + 3], w[v + 13]) + h5);
        o[v] = r;
    }

    if (i + VEC <= n) {
        float4* po = reinterpret_cast<float4*>(out + i);
        po[0] = make_float4(o[0], o[1], o[2], o[3]);
        po[1] = make_float4(o[4], o[5], o[6], o[7]);
    } else {
        #pragma unroll
        for (int v = 0; v < VEC; v++) {
            if (i + v < n) out[i + v] = o[v];
        }
    }
}

extern "C" void kernel_launch(void* const* d_in, const int* in_sizes, int n_in,
                              void* d_out, int out_size)
{
    const float* x       = (const float*)d_in[0];
    const float* scale_p = (const float*)d_in[1];
    float*       out     = (float*)d_out;
    int n = in_sizes[0];

    int threads = (n + VEC - 1) / VEC;
    int blocks  = (threads + BLOCK - 1) / BLOCK;
    dilate1d_kernel<<<blocks, BLOCK>>>(x, scale_p, out, n);
}